// round 6
// baseline (speedup 1.0000x reference)
#include <cuda_runtime.h>
#include <cuda_bf16.h>
#include <stdint.h>
#include <math.h>

// ---------------- problem constants ----------------
#define NTOT  4096
#define DIM   512
#define BHALF 2048
#define INV_TEMP 10.0f

// ---------------- GEMM tiling ----------------
#define BM 128
#define BN 128
#define BKC 64            // K elements per pipeline chunk (128 bytes/row)
#define NKCH (DIM / BKC)  // 8
#define NCHUNK 32         // 128-wide column chunks for partials
#define NTILES 528        // 32*33/2 triangular tiles
#define STAGE 32768       // bytes per pipeline stage (A 16KB + B 16KB)

// ---------------- device scratch (no allocs) ----------------
__device__ __nv_bfloat16 g_fb[NTOT * DIM];     // quantized features, bf16 (4 MB)
__device__ float g_rinv[NTOT];                 // 1 / ||q_i||
__device__ float g_part[NCHUNK * NTOT];        // per-(chunk,row) exp-sum partials
__device__ float g_pos[NTOT];                  // sim[i, (i+B)%N]
__device__ float g_blk[32];                    // finalize block partials
__device__ unsigned g_ctr = 0;                 // finalize completion counter

// ---------------- helpers ----------------
static __device__ __forceinline__ uint32_t smem_u32(const void* p) {
    uint32_t a;
    asm("{ .reg .u64 t; cvta.to.shared.u64 t, %1; cvt.u32.u64 %0, t; }"
        : "=r"(a) : "l"(p));
    return a;
}

static __device__ __forceinline__ void ldm_x4(uint32_t r[4], uint32_t addr) {
    asm volatile("ldmatrix.sync.aligned.m8n8.x4.shared.b16 {%0,%1,%2,%3}, [%4];"
                 : "=r"(r[0]), "=r"(r[1]), "=r"(r[2]), "=r"(r[3]) : "r"(addr));
}

static __device__ __forceinline__ void mma16816(float c[4], const uint32_t a[4],
                                                uint32_t b0, uint32_t b1) {
    asm volatile(
        "mma.sync.aligned.m16n8k16.row.col.f32.bf16.bf16.f32 "
        "{%0,%1,%2,%3}, {%4,%5,%6,%7}, {%8,%9}, {%0,%1,%2,%3};"
        : "+f"(c[0]), "+f"(c[1]), "+f"(c[2]), "+f"(c[3])
        : "r"(a[0]), "r"(a[1]), "r"(a[2]), "r"(a[3]), "r"(b0), "r"(b1));
}

#define SWZ(off) ((off) ^ (((off) >> 3) & 0x70))

// ---------------------------------------------------------------------------
// Kernel 1a: pure streaming fp32 -> bf16 convert. No barriers, no shuffles.
// grid = 1024 x 256; each thread converts 2 consecutive float4 (32B in, 16B out).
// ---------------------------------------------------------------------------
__global__ __launch_bounds__(256) void convert_kernel(const float* __restrict__ in) {
    const size_t i = ((size_t)blockIdx.x * 256 + threadIdx.x) * 2;  // float4 index
    const float4* p = reinterpret_cast<const float4*>(in);
    float4 a = p[i];
    float4 b = p[i + 1];
    __nv_bfloat162 a0 = __floats2bfloat162_rn(a.x, a.y);
    __nv_bfloat162 a1 = __floats2bfloat162_rn(a.z, a.w);
    __nv_bfloat162 b0 = __floats2bfloat162_rn(b.x, b.y);
    __nv_bfloat162 b1 = __floats2bfloat162_rn(b.z, b.w);
    uint4 o;
    o.x = *reinterpret_cast<uint32_t*>(&a0);
    o.y = *reinterpret_cast<uint32_t*>(&a1);
    o.z = *reinterpret_cast<uint32_t*>(&b0);
    o.w = *reinterpret_cast<uint32_t*>(&b1);
    *reinterpret_cast<uint4*>(g_fb + i * 4) = o;
}

// ---------------------------------------------------------------------------
// Kernel 1b: per-row inverse norm from the bf16 data (hot in L2).
// One warp per row; 8 warps per block.
// ---------------------------------------------------------------------------
__global__ __launch_bounds__(256) void norm_kernel() {
    const int row = blockIdx.x * 8 + (threadIdx.x >> 5);
    const int lane = threadIdx.x & 31;
    const uint4* q = reinterpret_cast<const uint4*>(g_fb + (size_t)row * DIM);

    float ss = 0.f;
    #pragma unroll
    for (int it = 0; it < 2; ++it) {
        uint4 v = q[lane + it * 32];
        const uint32_t w[4] = {v.x, v.y, v.z, v.w};
        #pragma unroll
        for (int k = 0; k < 4; ++k) {
            float2 f = __bfloat1622float2(*reinterpret_cast<const __nv_bfloat162*>(&w[k]));
            ss += f.x * f.x + f.y * f.y;
        }
    }
    #pragma unroll
    for (int off = 16; off > 0; off >>= 1)
        ss += __shfl_xor_sync(0xffffffffu, ss, off);
    if (lane == 0)
        g_rinv[row] = 1.0f / fmaxf(sqrtf(ss), 1e-12f);
}

// ---------------------------------------------------------------------------
// Kernel 2: triangular bf16 HMMA GEMM (128x128 tiles, bx >= by), 4 warps with
// 64x64 warp tiles, 3-stage cp.async pipeline. Epilogue folds normalization
// (rinv_i * rinv_j) and produces row + transposed-column exp-sum partials.
// ---------------------------------------------------------------------------
static __device__ __forceinline__ void load_chunk_async(uint32_t sbase, int buf,
                                                        int tid, int row0, int col0,
                                                        int kc) {
    const __nv_bfloat16* F = g_fb;
    const uint32_t A = sbase + buf * STAGE;
    const uint32_t B = A + 16384;
    const int k0 = kc * BKC;

    #pragma unroll
    for (int it = 0; it < 8; ++it) {
        int u = tid + it * 128;
        int r = u >> 3, cg = u & 7;
        uint32_t so = SWZ((uint32_t)(r * 128 + cg * 16));
        const void* g = F + (size_t)(row0 + r) * DIM + k0 + cg * 8;
        asm volatile("cp.async.cg.shared.global [%0], [%1], 16;" :: "r"(A + so), "l"(g));
    }
    #pragma unroll
    for (int it = 0; it < 8; ++it) {
        int u = tid + it * 128;
        int r = u >> 3, cg = u & 7;
        uint32_t so = SWZ((uint32_t)(r * 128 + cg * 16));
        const void* g = F + (size_t)(col0 + r) * DIM + k0 + cg * 8;
        asm volatile("cp.async.cg.shared.global [%0], [%1], 16;" :: "r"(B + so), "l"(g));
    }
    asm volatile("cp.async.commit_group;" ::: "memory");
}

__global__ void __launch_bounds__(128, 2) sim_kernel() {
    extern __shared__ char sm_raw[];
    __shared__ float s_rinv_r[128];
    __shared__ float s_rinv_c[128];
    __shared__ float smem_row[128 * 2];   // [row][wn]
    __shared__ float smem_col[128 * 2];   // [col][wm]

    char* smem = (char*)(((uintptr_t)sm_raw + 1023) & ~(uintptr_t)1023);
    const uint32_t sbase = smem_u32(smem);

    // triangular decode: t -> (bx, by) with bx >= by, t = bx*(bx+1)/2 + by
    const int t = blockIdx.x;
    int bx = (int)((sqrtf(8.0f * (float)t + 1.0f) - 1.0f) * 0.5f);
    while ((bx + 1) * (bx + 2) / 2 <= t) ++bx;
    while (bx * (bx + 1) / 2 > t) --bx;
    const int by = t - bx * (bx + 1) / 2;

    const int tid = threadIdx.x;
    const int lane = tid & 31;
    const int wid = tid >> 5;
    const int wm = wid & 1;           // 0..1: 64-row slice
    const int wn = wid >> 1;          // 0..1: 64-col slice
    const int row0 = by * BM;
    const int col0 = bx * BN;

    // stage per-tile inverse norms
    s_rinv_r[tid] = g_rinv[row0 + tid];
    s_rinv_c[tid] = g_rinv[col0 + tid];

    float acc[4][8][4];
    #pragma unroll
    for (int mi = 0; mi < 4; ++mi)
        #pragma unroll
        for (int ni = 0; ni < 8; ++ni)
            #pragma unroll
            for (int q = 0; q < 4; ++q) acc[mi][ni][q] = 0.f;

    const int aRowB = wm * 64 + ((lane >> 3) & 1) * 8 + (lane & 7);
    const uint32_t aKoff = (uint32_t)((lane >> 4) * 16);
    const int bRowB = wn * 64 + ((lane >> 4) & 1) * 8 + (lane & 7);
    const uint32_t bKoff = (uint32_t)(((lane >> 3) & 1) * 16);

    // ---- 3-stage pipelined mainloop, one sync per chunk ----
    load_chunk_async(sbase, 0, tid, row0, col0, 0);
    load_chunk_async(sbase, 1, tid, row0, col0, 1);

    #pragma unroll
    for (int c = 0; c < NKCH; ++c) {
        if (c < NKCH - 1) {
            asm volatile("cp.async.wait_group 1;" ::: "memory");
        } else {
            asm volatile("cp.async.wait_group 0;" ::: "memory");
        }
        __syncthreads();
        if (c + 2 < NKCH)
            load_chunk_async(sbase, (c + 2) % 3, tid, row0, col0, c + 2);

        const uint32_t A = sbase + (c % 3) * STAGE;
        const uint32_t B = A + 16384;

        #pragma unroll
        for (int kk = 0; kk < 4; ++kk) {
            uint32_t a[4][4];
            #pragma unroll
            for (int mi = 0; mi < 4; ++mi) {
                uint32_t off = (uint32_t)((aRowB + mi * 16) * 128) + aKoff + kk * 32;
                ldm_x4(a[mi], A + SWZ(off));
            }
            uint32_t bb[4][4];
            #pragma unroll
            for (int nb = 0; nb < 4; ++nb) {
                uint32_t off = (uint32_t)((bRowB + nb * 16) * 128) + bKoff + kk * 32;
                ldm_x4(bb[nb], B + SWZ(off));
            }
            #pragma unroll
            for (int mi = 0; mi < 4; ++mi)
                #pragma unroll
                for (int ni = 0; ni < 8; ++ni)
                    mma16816(acc[mi][ni], a[mi],
                             bb[ni >> 1][(ni & 1) * 2], bb[ni >> 1][(ni & 1) * 2 + 1]);
        }
    }

    // ---- epilogue: normalize, exp, row + transposed column partials ----
    const bool isPosTile = (bx - by == 16);
    float erow[8] = {0.f, 0.f, 0.f, 0.f, 0.f, 0.f, 0.f, 0.f};

    // per-thread row metadata
    float rowinv[8];
    int rowloc[8];
    #pragma unroll
    for (int rg = 0; rg < 8; ++rg) {
        const int mi = rg >> 1, half = rg & 1;
        rowloc[rg] = wm * 64 + mi * 16 + half * 8 + (lane >> 2);
        rowinv[rg] = s_rinv_r[rowloc[rg]];
    }

    #pragma unroll
    for (int ni = 0; ni < 8; ++ni) {
        #pragma unroll
        for (int q = 0; q < 2; ++q) {
            const int gjloc = wn * 64 + ni * 8 + (lane & 3) * 2 + q;
            const int gj = col0 + gjloc;
            const float cinv = s_rinv_c[gjloc];
            float ecol = 0.f;
            #pragma unroll
            for (int rg = 0; rg < 8; ++rg) {
                const int mi = rg >> 1, half = rg & 1;
                const float d = acc[mi][ni][half * 2 + q];
                const int giloc = rowloc[rg];
                const int gi = row0 + giloc;
                const float s = d * rowinv[rg] * cinv;
                if (isPosTile && gjloc == giloc) {
                    g_pos[gi] = s;       // row gi's positive
                    g_pos[gj] = s;       // row gj's positive (symmetric)
                }
                const float e = (gj != gi) ? __expf(INV_TEMP * s) : 0.f;
                erow[rg] += e;
                ecol += e;
            }
            ecol += __shfl_xor_sync(0xffffffffu, ecol, 4);
            ecol += __shfl_xor_sync(0xffffffffu, ecol, 8);
            ecol += __shfl_xor_sync(0xffffffffu, ecol, 16);
            if ((lane >> 2) == 0)
                smem_col[gjloc * 2 + wm] = ecol;
        }
    }

    #pragma unroll
    for (int rg = 0; rg < 8; ++rg) {
        float e = erow[rg];
        e += __shfl_xor_sync(0xffffffffu, e, 1);
        e += __shfl_xor_sync(0xffffffffu, e, 2);
        if ((lane & 3) == 0)
            smem_row[rowloc[rg] * 2 + wn] = e;
    }
    __syncthreads();

    {
        const float pr = smem_row[tid * 2] + smem_row[tid * 2 + 1];
        g_part[(size_t)bx * NTOT + row0 + tid] = pr;
        if (bx != by) {
            const float pc = smem_col[tid * 2] + smem_col[tid * 2 + 1];
            g_part[(size_t)by * NTOT + col0 + tid] = pc;
        }
    }
}

// ---------------------------------------------------------------------------
// Kernel 3: fused finalize. grid = 32 x 128 (one row per thread). Last block
// does the deterministic fixed-order final sum; counter self-resets.
// ---------------------------------------------------------------------------
__global__ __launch_bounds__(128) void finalize_kernel(float* __restrict__ out) {
    const int tid = threadIdx.x;
    const int row = blockIdx.x * 128 + tid;

    float s = 0.f;
    #pragma unroll
    for (int c = 0; c < NCHUNK; ++c)
        s += g_part[(size_t)c * NTOT + row];
    float local = logf(s) - INV_TEMP * g_pos[row];

    #pragma unroll
    for (int off = 16; off > 0; off >>= 1)
        local += __shfl_xor_sync(0xffffffffu, local, off);
    __shared__ float sm[4];
    if ((tid & 31) == 0) sm[tid >> 5] = local;
    __syncthreads();

    if (tid == 0) {
        float bsum = sm[0] + sm[1] + sm[2] + sm[3];
        g_blk[blockIdx.x] = bsum;
        __threadfence();
        const unsigned old = atomicAdd(&g_ctr, 1u);
        if (old == 31u) {
            __threadfence();
            float tot = 0.f;
            #pragma unroll
            for (int b = 0; b < 32; ++b) tot += g_blk[b];   // fixed order: deterministic
            out[0] = tot / (float)NTOT;
            g_ctr = 0u;   // reset for next graph replay
        }
    }
}

// ---------------------------------------------------------------------------
extern "C" void kernel_launch(void* const* d_in, const int* in_sizes, int n_in,
                              void* d_out, int out_size) {
    (void)in_sizes; (void)n_in; (void)out_size;
    const float* features = (const float*)d_in[0];
    float* out = (float*)d_out;

    const int dyn_smem = 3 * STAGE + 1024;   // 97 KB dynamic, 3-stage pipeline
    static bool attr_set = false;
    if (!attr_set) {
        cudaFuncSetAttribute(sim_kernel, cudaFuncAttributeMaxDynamicSharedMemorySize,
                             dyn_smem);
        attr_set = true;
    }

    convert_kernel<<<1024, 256>>>(features);
    norm_kernel<<<NTOT / 8, 256>>>();
    sim_kernel<<<NTILES, 128, dyn_smem>>>();
    finalize_kernel<<<32, 128>>>(out);
}